// round 7
// baseline (speedup 1.0000x reference)
#include <cuda_runtime.h>

#define RFN 512
#define TN  32
#define TQN 8                // t-rows per CTA (t-split factor 4)
#define KN  32
#define LN  2048
#define BK  32
#define NTILE (LN / BK)      // 64
#define STAGES 3
#define THREADS 32

__device__ float g_thr[RFN * TN * KN];   // thresholded potentials (2 MB)
__device__ int   g_cnt[RFN];             // per-branch completion tickets (reset after use)

// Packed double fp32 FMA (Blackwell FFMA2) — only reachable via PTX fma.rn.f32x2.
__device__ __forceinline__ unsigned long long ffma2(unsigned long long a,
                                                    unsigned long long b,
                                                    unsigned long long c) {
    unsigned long long d;
    asm volatile("fma.rn.f32x2 %0, %1, %2, %3;" : "=l"(d) : "l"(a), "l"(b), "l"(c));
    return d;
}

__device__ __forceinline__ void cp_async16(unsigned dst, const float* src) {
    asm volatile("cp.async.cg.shared.global [%0], [%1], 16;" :: "r"(dst), "l"(src) : "memory");
}

// 16B-chunk XOR swizzle: chunk (row, c4) lives at column (c4 ^ (row & 7)).
#define SWZ(row, c4) ((c4) ^ ((row) & 7))

// grid = 2048: branch r = bid>>2, t-quarter q = bid&3 (t rows q*8 .. q*8+7)
__global__ __launch_bounds__(THREADS)
void spyke_fused(const float* __restrict__ rec,   // (T=32, C=1, RF=512, L=2048)
                 const float* __restrict__ Wt,    // (RF=512, K=32, C=1, L=2048)
                 float* __restrict__ out)         // (T, 1, K, RF)
{
    __shared__ __align__(16) float As[STAGES][TQN][BK];   // 1 KB / stage, swizzled
    __shared__ __align__(16) float Bs[STAGES][KN][BK];    // 4 KB / stage, swizzled

    const int lane = threadIdx.x;      // 0..31
    const int rw = lane >> 2;          // 0..7 -> local t row (exactly one per thread)
    const int cw = lane & 3;           // 0..3 -> k cols {cw, cw+4, ..., cw+28}
    const int r  = blockIdx.x >> 2;
    const int tb = (blockIdx.x & 3) * TQN;   // global t base

    const float* Abase = rec + ((size_t)tb * RFN + r) * LN;   // row stride RFN*LN
    const float* Bbase = Wt  + (size_t)r * KN * LN;

    const unsigned sA = (unsigned)__cvta_generic_to_shared(&As[0][0][0]);
    const unsigned sB = (unsigned)__cvta_generic_to_shared(&Bs[0][0][0]);
    const unsigned STGA = TQN * BK * 4;   // 1024 B
    const unsigned STGB = KN * BK * 4;    // 4096 B

    // acc[c]: output (t = tb+rw, k = cw+4c); (even-l, odd-l) packed f32x2
    unsigned long long acc[8];
#pragma unroll
    for (int c = 0; c < 8; c++) acc[c] = 0ull;

    // ---- prologue: prefetch tiles 0..STAGES-2 ----
#pragma unroll
    for (int s = 0; s < STAGES - 1; s++) {
        const int l0 = s * BK;
#pragma unroll
        for (int i = 0; i < 2; i++) {            // A: 64 chunks / 32 lanes
            int idx = i * 32 + lane;
            int row = idx >> 3, c4 = idx & 7;
            unsigned soff = (unsigned)s * STGA + (unsigned)((row * BK + SWZ(row, c4) * 4) * 4);
            cp_async16(sA + soff, Abase + (size_t)row * (RFN * LN) + l0 + c4 * 4);
        }
#pragma unroll
        for (int i = 0; i < 8; i++) {            // B: 256 chunks / 32 lanes
            int idx = i * 32 + lane;
            int row = idx >> 3, c4 = idx & 7;
            unsigned soff = (unsigned)s * STGB + (unsigned)((row * BK + SWZ(row, c4) * 4) * 4);
            cp_async16(sB + soff, Bbase + (size_t)row * LN + l0 + c4 * 4);
        }
        asm volatile("cp.async.commit_group;" ::: "memory");
    }

    int buf = 0, pf = STAGES - 1;   // stage indices (wraparound counters)
    for (int ti = 0; ti < NTILE; ti++) {
        asm volatile("cp.async.wait_group %0;" :: "n"(STAGES - 2) : "memory");
        __syncwarp();   // warp-private pipeline

        if (ti + STAGES - 1 < NTILE) {
            const int l0 = (ti + STAGES - 1) * BK;
#pragma unroll
            for (int i = 0; i < 2; i++) {
                int idx = i * 32 + lane;
                int row = idx >> 3, c4 = idx & 7;
                unsigned soff = (unsigned)pf * STGA + (unsigned)((row * BK + SWZ(row, c4) * 4) * 4);
                cp_async16(sA + soff, Abase + (size_t)row * (RFN * LN) + l0 + c4 * 4);
            }
#pragma unroll
            for (int i = 0; i < 8; i++) {
                int idx = i * 32 + lane;
                int row = idx >> 3, c4 = idx & 7;
                unsigned soff = (unsigned)pf * STGB + (unsigned)((row * BK + SWZ(row, c4) * 4) * 4);
                cp_async16(sB + soff, Bbase + (size_t)row * LN + l0 + c4 * 4);
            }
        }
        asm volatile("cp.async.commit_group;" ::: "memory");
        if (++pf == STAGES) pf = 0;

        // ---- compute tile ti ----
#pragma unroll
        for (int lc4 = 0; lc4 < BK / 4; lc4++) {
            // A row rw (rows distinct mod 8 across warp -> 1 phase, 4-lane bcast)
            ulonglong2 av = *(const ulonglong2*)&As[buf][rw][(lc4 ^ rw) * 4];
            ulonglong2 bv[8];
#pragma unroll
            for (int c = 0; c < 8; c++) {
                const int row = cw + 4 * c;
                bv[c] = *(const ulonglong2*)&Bs[buf][row][(lc4 ^ (row & 7)) * 4];
            }
#pragma unroll
            for (int c = 0; c < 8; c++) {
                acc[c] = ffma2(av.x, bv[c].x, acc[c]);
                acc[c] = ffma2(av.y, bv[c].y, acc[c]);
            }
        }
        if (++buf == STAGES) buf = 0;
    }

    // ---- threshold, write to scratch g_thr[r][t][k] ----
    const int t_glob = tb + rw;
#pragma unroll
    for (int c = 0; c < 8; c++) {
        unsigned long long a = acc[c];
        float lo = __uint_as_float((unsigned)(a & 0xffffffffull));
        float hi = __uint_as_float((unsigned)(a >> 32));
        float pot = lo + hi;
        float tv  = (pot > 20.0f) ? pot : 0.0f;
        g_thr[((size_t)r * TN + t_glob) * KN + (cw + 4 * c)] = tv;
    }

    // ---- completion ticket; last of 4 CTAs runs kWTA + output for branch r ----
    __threadfence();
    int old = 0;
    if (lane == 0) old = atomicAdd(&g_cnt[r], 1);
    old = __shfl_sync(0xffffffffu, old, 0);
    if (old != 3) return;
    __threadfence();   // acquire: make all quarters' g_thr writes visible

    const float* thp = &g_thr[(size_t)r * TN * KN];
    float th_t[TN];
    int cnt = 0;
#pragma unroll
    for (int t = 0; t < TN; t++) {
        th_t[t] = thp[t * KN + lane];            // lane = feature k
        cnt += (th_t[t] > 0.0f) ? 1 : 0;
    }
    int first = 32 - cnt;
    if (first > 31) first = 31;                  // cnt==0 -> 31 ; cnt>=1 -> 0..31
    float vals = th_t[first];
    float vk = (cnt > 0) ? vals : 0.0f;
    float vmax = vk;
#pragma unroll
    for (int o = 16; o > 0; o >>= 1) {
        float ov = __shfl_xor_sync(0xffffffffu, vmax, o);
        vmax = (ov > vmax) ? ov : vmax;
    }
    const float v = vmax * 32.0f;
    const float total = (float)cnt * (vals + v);

    float cur = total;
    bool win = false;
#pragma unroll
    for (int it = 0; it < 4; it++) {
        float bvv = cur;
        int bi = lane;
#pragma unroll
        for (int o = 16; o > 0; o >>= 1) {
            float ov = __shfl_xor_sync(0xffffffffu, bvv, o);
            int   oi = __shfl_xor_sync(0xffffffffu, bi, o);
            if (ov > bvv || (ov == bvv && oi < bi)) { bvv = ov; bi = oi; }
        }
        if (lane == bi) {
            if (cur > 0.0f) win = true;          // valid = top_val != 0
            cur = -1.0f;                         // exclude from later rounds
        }
    }

    // out[t,0,k,r] = (thr>0 && k is winner) ? 1 : 0
#pragma unroll
    for (int t = 0; t < TN; t++) {
        out[(size_t)t * (KN * RFN) + (size_t)lane * RFN + r] =
            (win && th_t[t] > 0.0f) ? 1.0f : 0.0f;
    }

    // reset ticket for the next graph replay (deterministic across calls)
    if (lane == 0) g_cnt[r] = 0;
}

extern "C" void kernel_launch(void* const* d_in, const int* in_sizes, int n_in,
                              void* d_out, int out_size) {
    const float* rec = (const float*)d_in[0];   // rec_field (32,1,512,2048)
    const float* Wt  = (const float*)d_in[1];   // W (512,32,1,2048)
    // d_in[2] = reward — unused by the reference output
    float* out = (float*)d_out;                 // (32,1,32,512)
    spyke_fused<<<RFN * 4, THREADS>>>(rec, Wt, out);
}

// round 8
// speedup vs baseline: 1.8621x; 1.8621x over previous
#include <cuda_runtime.h>

#define RFN 512
#define TN  32
#define KN  32
#define LN  2048
#define LQ  512              // L per quarter (l-split x4)
#define BK  32
#define NTILE (LQ / BK)      // 16
#define STAGES 2
#define NCTA (256 * 4)       // 256 branch-pairs x 4 l-quarters

__device__ unsigned long long g_part[NCTA][64][32];  // [cta][accidx][lane] 16.8 MB
__device__ int g_cnt[256];                           // per-pair tickets (reset after use)

// Packed double fp32 FMA / ADD (Blackwell f32x2) — PTX only.
__device__ __forceinline__ unsigned long long ffma2(unsigned long long a,
                                                    unsigned long long b,
                                                    unsigned long long c) {
    unsigned long long d;
    asm volatile("fma.rn.f32x2 %0, %1, %2, %3;" : "=l"(d) : "l"(a), "l"(b), "l"(c));
    return d;
}
__device__ __forceinline__ unsigned long long add2(unsigned long long a,
                                                   unsigned long long b) {
    unsigned long long d;
    asm volatile("add.rn.f32x2 %0, %1, %2;" : "=l"(d) : "l"(a), "l"(b));
    return d;
}

__device__ __forceinline__ void cp_async16(unsigned dst, const float* src) {
    asm volatile("cp.async.cg.shared.global [%0], [%1], 16;" :: "r"(dst), "l"(src) : "memory");
}

// 16B-chunk swizzle; branch b gets ^4 so its bank-quads complement branch a's.
#define SWZ(row, c4, b) (((c4) ^ ((row) & 7) ^ ((b) << 2)) & 7)

// grid = 1024: pair = bid>>2 (branches 2p, 2p+1), q = bid&3 (l range q*512..+511)
// block = 32: lanes 0-15 -> branch 2p, lanes 16-31 -> branch 2p+1; per-lane 8t x 8k.
__global__ __launch_bounds__(32)
void spyke_gemm(const float* __restrict__ rec,   // (T=32, C=1, RF=512, L=2048)
                const float* __restrict__ Wt,    // (RF=512, K=32, C=1, L=2048)
                float* __restrict__ out)         // (T, 1, K, RF)
{
    __shared__ __align__(16) float As[STAGES][2][TN][BK];   // 8 KB/stage
    __shared__ __align__(16) float Bs[STAGES][2][KN][BK];   // 8 KB/stage

    const int lane = threadIdx.x;
    const int bsel = lane >> 4;        // which branch of the pair
    const int l16  = lane & 15;
    const int rg   = l16 >> 2;         // 0..3 -> t rows {rg+4j, j=0..7}
    const int cg   = l16 & 3;          // 0..3 -> k cols {cg+4c, c=0..7}
    const int pair = blockIdx.x >> 2;
    const int q    = blockIdx.x & 3;
    const int lqb  = q * LQ;

    const unsigned sA = (unsigned)__cvta_generic_to_shared(&As[0][0][0][0]);
    const unsigned sB = (unsigned)__cvta_generic_to_shared(&Bs[0][0][0][0]);

    unsigned long long acc[8][8];
#pragma unroll
    for (int j = 0; j < 8; j++)
#pragma unroll
        for (int c = 0; c < 8; c++) acc[j][c] = 0ull;

    // ---------- tile filler: 32 cp.async (A: 16, B: 16), 4 wf each ----------
    auto fill = [&](int s, int l0) {
#pragma unroll
        for (int i = 0; i < 16; i++) {           // A chunks: 2 branches x 32 rows x 8 c4
            int chunk = i * 32 + lane;           // 0..511
            int wb  = chunk >> 8;
            int rem = chunk & 255;
            int row = rem >> 3, c4 = rem & 7;
            unsigned dst = sA + (unsigned)((((s * 2 + wb) * TN + row) * BK + SWZ(row, c4, wb) * 4) * 4);
            cp_async16(dst, rec + ((size_t)row * RFN + pair * 2 + wb) * LN + l0 + c4 * 4);
        }
#pragma unroll
        for (int i = 0; i < 16; i++) {           // B chunks
            int chunk = i * 32 + lane;
            int wb  = chunk >> 8;
            int rem = chunk & 255;
            int row = rem >> 3, c4 = rem & 7;
            unsigned dst = sB + (unsigned)((((s * 2 + wb) * KN + row) * BK + SWZ(row, c4, wb) * 4) * 4);
            cp_async16(dst, Wt + ((size_t)(pair * 2 + wb) * KN + row) * LN + l0 + c4 * 4);
        }
        asm volatile("cp.async.commit_group;" ::: "memory");
    };

    fill(0, lqb);

    for (int ti = 0; ti < NTILE; ti++) {
        asm volatile("cp.async.wait_group 0;" ::: "memory");
        __syncwarp();
        if (ti + 1 < NTILE) fill((ti + 1) & 1, lqb + (ti + 1) * BK);

        const int s = ti & 1;
#pragma unroll
        for (int lc4 = 0; lc4 < BK / 4; lc4++) {
            ulonglong2 bv[8];
#pragma unroll
            for (int c = 0; c < 8; c++) {
                const int row = cg + 4 * c;
                bv[c] = *(const ulonglong2*)&Bs[s][bsel][row][SWZ(row, lc4, bsel) * 4];
            }
#pragma unroll
            for (int j = 0; j < 8; j++) {
                const int row = rg + 4 * j;
                ulonglong2 av = *(const ulonglong2*)&As[s][bsel][row][SWZ(row, lc4, bsel) * 4];
#pragma unroll
                for (int c = 0; c < 8; c++) {
                    acc[j][c] = ffma2(av.x, bv[c].x, acc[j][c]);
                    acc[j][c] = ffma2(av.y, bv[c].y, acc[j][c]);
                }
            }
        }
    }

    // ---------- store packed partials (coalesced: 32 lanes x 8B per accidx) ----------
    {
        unsigned long long* dst = &g_part[blockIdx.x][0][0];
#pragma unroll
        for (int j = 0; j < 8; j++)
#pragma unroll
            for (int c = 0; c < 8; c++)
                dst[(j * 8 + c) * 32 + lane] = acc[j][c];
    }

    __threadfence();
    int old = 0;
    if (lane == 0) old = atomicAdd(&g_cnt[pair], 1);
    old = __shfl_sync(0xffffffffu, old, 0);
    if (old != 3) return;
    __threadfence();   // acquire: all quarters' partials visible

    // ---------- finisher: combine quarters, threshold, kWTA, write output ----------
    float* thr_sh = (float*)&As[0][0][0][0];     // reuse dead tile smem: [t][lane], stride 33

    for (int bs = 0; bs < 2; bs++) {
        const int r = pair * 2 + bs;             // lane = feature k
        float th[TN];
        int cnt = 0;
#pragma unroll
        for (int t = 0; t < TN; t++) {
            const int accidx = (t >> 2) * 8 + (lane >> 2);
            const int glane  = bs * 16 + (t & 3) * 4 + (lane & 3);
            unsigned long long p0 = g_part[pair * 4 + 0][accidx][glane];
            unsigned long long p1 = g_part[pair * 4 + 1][accidx][glane];
            unsigned long long p2 = g_part[pair * 4 + 2][accidx][glane];
            unsigned long long p3 = g_part[pair * 4 + 3][accidx][glane];
            unsigned long long sall = add2(add2(p0, p1), add2(p2, p3));
            float lo = __uint_as_float((unsigned)(sall & 0xffffffffull));
            float hi = __uint_as_float((unsigned)(sall >> 32));
            float pot = lo + hi;
            float tv = (pot > 20.0f) ? pot : 0.0f;
            th[t] = tv;
            cnt += (tv > 0.0f) ? 1 : 0;
            thr_sh[t * 33 + lane] = tv;          // for dynamic 'first' index
        }
        int first = 32 - cnt;
        if (first > 31) first = 31;              // cnt==0 -> 31 ; cnt>=1 -> 0..31
        float vals = thr_sh[first * 33 + lane];
        float vk = (cnt > 0) ? vals : 0.0f;
        float vmax = vk;
#pragma unroll
        for (int o = 16; o > 0; o >>= 1) {
            float ov = __shfl_xor_sync(0xffffffffu, vmax, o);
            vmax = (ov > vmax) ? ov : vmax;
        }
        const float v = vmax * 32.0f;
        const float total = (float)cnt * (vals + v);

        float cur = total;
        bool win = false;
#pragma unroll
        for (int it = 0; it < 4; it++) {
            float bvv = cur;
            int bi = lane;
#pragma unroll
            for (int o = 16; o > 0; o >>= 1) {
                float ov = __shfl_xor_sync(0xffffffffu, bvv, o);
                int   oi = __shfl_xor_sync(0xffffffffu, bi, o);
                if (ov > bvv || (ov == bvv && oi < bi)) { bvv = ov; bi = oi; }
            }
            if (lane == bi) {
                if (cur > 0.0f) win = true;      // valid = top_val != 0
                cur = -1.0f;                     // exclude from later rounds
            }
        }

#pragma unroll
        for (int t = 0; t < TN; t++) {
            out[(size_t)t * (KN * RFN) + (size_t)lane * RFN + r] =
                (win && th[t] > 0.0f) ? 1.0f : 0.0f;
        }
    }

    if (lane == 0) g_cnt[pair] = 0;              // reset for next graph replay
}

extern "C" void kernel_launch(void* const* d_in, const int* in_sizes, int n_in,
                              void* d_out, int out_size) {
    const float* rec = (const float*)d_in[0];   // rec_field (32,1,512,2048)
    const float* Wt  = (const float*)d_in[1];   // W (512,32,1,2048)
    // d_in[2] = reward — unused by the reference output
    float* out = (float*)d_out;                 // (32,1,32,512)
    spyke_gemm<<<NCTA, 32>>>(rec, Wt, out);
}

// round 9
// speedup vs baseline: 2.1937x; 1.1780x over previous
#include <cuda_runtime.h>

#define RFN 512
#define TN  32
#define KN  32
#define LN  2048
#define LH  1024             // L per half (l-split x2)
#define BK  32
#define NTILE (LH / BK)      // 32
#define STAGES 3
#define NCTA (RFN * 2)       // 1024: branch = bid>>1, half = bid&1

__device__ unsigned long long g_part[NCTA][32][32];  // [cta][accidx][lane] 8.4 MB
__device__ int g_cnt[RFN];                           // per-branch tickets (reset after use)

// Packed double fp32 FMA / ADD (Blackwell f32x2) — PTX only.
__device__ __forceinline__ unsigned long long ffma2(unsigned long long a,
                                                    unsigned long long b,
                                                    unsigned long long c) {
    unsigned long long d;
    asm volatile("fma.rn.f32x2 %0, %1, %2, %3;" : "=l"(d) : "l"(a), "l"(b), "l"(c));
    return d;
}
__device__ __forceinline__ unsigned long long add2(unsigned long long a,
                                                   unsigned long long b) {
    unsigned long long d;
    asm volatile("add.rn.f32x2 %0, %1, %2;" : "=l"(d) : "l"(a), "l"(b));
    return d;
}

__device__ __forceinline__ void cp_async16(unsigned dst, const float* src) {
    asm volatile("cp.async.cg.shared.global [%0], [%1], 16;" :: "r"(dst), "l"(src) : "memory");
}

// 16B-chunk XOR swizzle: chunk (row, c4) lives at column (c4 ^ (row & 7)).
#define SWZ(row, c4) ((c4) ^ ((row) & 7))

__global__ __launch_bounds__(32)
void spyke_gemm(const float* __restrict__ rec,   // (T=32, C=1, RF=512, L=2048)
                const float* __restrict__ Wt,    // (RF=512, K=32, C=1, L=2048)
                float* __restrict__ out)         // (T, 1, K, RF)
{
    __shared__ __align__(16) float As[STAGES][TN][BK];   // 4 KB / stage, swizzled
    __shared__ __align__(16) float Bs[STAGES][KN][BK];

    const int lane = threadIdx.x;      // 0..31
    const int rg = lane >> 2;          // 0..7 -> t rows {rg+8j, j=0..3}
    const int cg = lane & 3;           // 0..3 -> k cols {cg+4c, c=0..7}
    const int r  = blockIdx.x >> 1;
    const int h  = blockIdx.x & 1;
    const int lb = h * LH;             // l base for this half

    const float* Abase = rec + (size_t)r * LN;          // + row*RFN*LN per t
    const float* Bbase = Wt  + (size_t)r * KN * LN;     // + row*LN per k

    const unsigned sA = (unsigned)__cvta_generic_to_shared(&As[0][0][0]);
    const unsigned sB = (unsigned)__cvta_generic_to_shared(&Bs[0][0][0]);
    const unsigned STG = TN * BK * 4;  // 4096 B per stage (A and B alike)

    // acc[j][c]: output (t = rg+8j, k = cg+4c); (even-l, odd-l) packed f32x2
    unsigned long long acc[4][8];
#pragma unroll
    for (int j = 0; j < 4; j++)
#pragma unroll
        for (int c = 0; c < 8; c++) acc[j][c] = 0ull;

    // ---- tile filler: 16 cp.async per lane (A:8, B:8) ----
    auto fill = [&](int s, int l0) {
#pragma unroll
        for (int i = 0; i < 8; i++) {            // A: 256 chunks / 32 lanes
            int idx = i * 32 + lane;
            int row = idx >> 3, c4 = idx & 7;
            unsigned soff = (unsigned)s * STG + (unsigned)((row * BK + SWZ(row, c4) * 4) * 4);
            cp_async16(sA + soff, Abase + (size_t)row * (RFN * LN) + l0 + c4 * 4);
        }
#pragma unroll
        for (int i = 0; i < 8; i++) {            // B: 256 chunks / 32 lanes
            int idx = i * 32 + lane;
            int row = idx >> 3, c4 = idx & 7;
            unsigned soff = (unsigned)s * STG + (unsigned)((row * BK + SWZ(row, c4) * 4) * 4);
            cp_async16(sB + soff, Bbase + (size_t)row * LN + l0 + c4 * 4);
        }
        asm volatile("cp.async.commit_group;" ::: "memory");
    };

    // ---- prologue: prefetch tiles 0,1 ----
    fill(0, lb);
    fill(1, lb + BK);

    int buf = 0, pf = STAGES - 1;
    for (int ti = 0; ti < NTILE; ti++) {
        asm volatile("cp.async.wait_group %0;" :: "n"(STAGES - 2) : "memory");
        __syncwarp();   // warp-private pipeline

        if (ti + STAGES - 1 < NTILE) {
            fill(pf, lb + (ti + STAGES - 1) * BK);
        } else {
            asm volatile("cp.async.commit_group;" ::: "memory");  // keep group count in step
        }
        if (++pf == STAGES) pf = 0;

        // ---- compute tile ti ----
#pragma unroll
        for (int lc4 = 0; lc4 < BK / 4; lc4++) {
            ulonglong2 av[4], bv[8];
#pragma unroll
            for (int j = 0; j < 4; j++) {
                const int row = rg + 8 * j;               // row&7 == rg
                av[j] = *(const ulonglong2*)&As[buf][row][(lc4 ^ rg) * 4];
            }
#pragma unroll
            for (int c = 0; c < 8; c++) {
                const int row = cg + 4 * c;
                bv[c] = *(const ulonglong2*)&Bs[buf][row][(lc4 ^ (row & 7)) * 4];
            }
#pragma unroll
            for (int j = 0; j < 4; j++)
#pragma unroll
                for (int c = 0; c < 8; c++) {
                    acc[j][c] = ffma2(av[j].x, bv[c].x, acc[j][c]);
                    acc[j][c] = ffma2(av[j].y, bv[c].y, acc[j][c]);
                }
        }
        if (++buf == STAGES) buf = 0;
    }

    // ---- store packed partials (coalesced: 32 lanes x 8B per accidx) ----
    {
        unsigned long long* dst = &g_part[blockIdx.x][0][0];
#pragma unroll
        for (int j = 0; j < 4; j++)
#pragma unroll
            for (int c = 0; c < 8; c++)
                dst[(j * 8 + c) * 32 + lane] = acc[j][c];
    }

    __threadfence();
    int old = 0;
    if (lane == 0) old = atomicAdd(&g_cnt[r], 1);
    old = __shfl_sync(0xffffffffu, old, 0);
    if (old != 1) return;
    __threadfence();   // acquire: both halves' partials visible

    // ---- finisher: combine halves, threshold, kWTA, write output (lane = k) ----
    float* thr_sh = (float*)&As[0][0][0];        // reuse dead tile smem: [t][33]

    float th[TN];
    int cnt = 0;
#pragma unroll
    for (int t = 0; t < TN; t++) {
        // inverse of acc mapping: lane' = (t&7)*4 + (k&3), accidx = (t>>3)*8 + (k>>2)
        const int accidx = (t >> 3) * 8 + (lane >> 2);
        const int glane  = (t & 7) * 4 + (lane & 3);
        unsigned long long p0 = g_part[r * 2 + 0][accidx][glane];
        unsigned long long p1 = g_part[r * 2 + 1][accidx][glane];
        unsigned long long s2 = add2(p0, p1);
        float lo = __uint_as_float((unsigned)(s2 & 0xffffffffull));
        float hi = __uint_as_float((unsigned)(s2 >> 32));
        float pot = lo + hi;
        float tv = (pot > 20.0f) ? pot : 0.0f;
        th[t] = tv;
        cnt += (tv > 0.0f) ? 1 : 0;
        thr_sh[t * 33 + lane] = tv;              // for dynamic 'first' lookup
    }
    int first = 32 - cnt;
    if (first > 31) first = 31;                  // cnt==0 -> 31 ; cnt>=1 -> 0..31
    float vals = thr_sh[first * 33 + lane];
    float vk = (cnt > 0) ? vals : 0.0f;
    float vmax = vk;
#pragma unroll
    for (int o = 16; o > 0; o >>= 1) {
        float ov = __shfl_xor_sync(0xffffffffu, vmax, o);
        vmax = (ov > vmax) ? ov : vmax;
    }
    const float v = vmax * 32.0f;
    const float total = (float)cnt * (vals + v);

    float cur = total;
    bool win = false;
#pragma unroll
    for (int it = 0; it < 4; it++) {
        float bvv = cur;
        int bi = lane;
#pragma unroll
        for (int o = 16; o > 0; o >>= 1) {
            float ov = __shfl_xor_sync(0xffffffffu, bvv, o);
            int   oi = __shfl_xor_sync(0xffffffffu, bi, o);
            if (ov > bvv || (ov == bvv && oi < bi)) { bvv = ov; bi = oi; }
        }
        if (lane == bi) {
            if (cur > 0.0f) win = true;          // valid = top_val != 0
            cur = -1.0f;                         // exclude from later rounds
        }
    }

    // out[t,0,k,r] = (thr>0 && k is winner) ? 1 : 0
#pragma unroll
    for (int t = 0; t < TN; t++) {
        out[(size_t)t * (KN * RFN) + (size_t)lane * RFN + r] =
            (win && th[t] > 0.0f) ? 1.0f : 0.0f;
    }

    if (lane == 0) g_cnt[r] = 0;                 // reset for next graph replay
}

extern "C" void kernel_launch(void* const* d_in, const int* in_sizes, int n_in,
                              void* d_out, int out_size) {
    const float* rec = (const float*)d_in[0];   // rec_field (32,1,512,2048)
    const float* Wt  = (const float*)d_in[1];   // W (512,32,1,2048)
    // d_in[2] = reward — unused by the reference output
    float* out = (float*)d_out;                 // (32,1,32,512)
    spyke_gemm<<<NCTA, 32>>>(rec, Wt, out);
}